// round 12
// baseline (speedup 1.0000x reference)
#include <cuda_runtime.h>
#include <cuda_fp16.h>
#include <cstdint>

// Problem constants
#define N_DIM 256
#define L_DIM 2048
#define B_DIM 128
#define CHK   128
#define NCHUNK 16
#define PGRID 296
#define POSTG 128

// ---------------------------------------------------------------------------
// Device global scratch
// ---------------------------------------------------------------------------
__device__ float g_P2[N_DIM][N_DIM];                // dA^256 fp32 (T^2)
__device__ float g_PT[N_DIM][N_DIM];                // P128^T fp32
__device__ float g_K[CHK][N_DIM];                   // Kvec fp32
__device__ float g_E[NCHUNK][B_DIM][N_DIM];         // chunk-end conv values
__device__ float g_F[NCHUNK][B_DIM][N_DIM];         // F_j = E_j + E_{j-1} T
__device__ float g_Xf[2][2][B_DIM][N_DIM];          // fp32 X ping-pong per parity
__device__ float g_Ppart[256][4096];                // split-K partial tiles
__device__ unsigned g_tilecnt[256];                 // split-K arrival counters
__device__ __half g_Pq[CHK + 1][N_DIM][N_DIM];      // P hi (natural [i][k])
__device__ __half g_Pl[CHK + 1][N_DIM][N_DIM];      // P lo (natural)
__device__ __half g_PqT[CHK + 1][N_DIM][N_DIM];     // P hi transposed [k][i]->P[i][k]? see note
__device__ __half g_PlT[CHK + 1][N_DIM][N_DIM];     // P lo transposed
// note: g_PqT[p][a][b] = P[p][b][a]
__device__ __half g_KTq[N_DIM][CHK];                // fp16 K transposed
__device__ __half g_uRq8[8][NCHUNK][B_DIM][256];    // 8 byte-shift copies of reversed u
__device__ __half g_Xq[NCHUNK][B_DIM][N_DIM];       // fp16 X_{c-1} (c>=1)
__device__ unsigned g_barctr;
__device__ unsigned g_barctr2;

// ---------------------------------------------------------------------------
// helpers
// ---------------------------------------------------------------------------
__device__ __forceinline__ void ffma2(float2& c, float2 a, float2 b) {
    asm("{\n\t"
        ".reg .b64 ra, rb, rc;\n\t"
        "mov.b64 ra, {%2, %3};\n\t"
        "mov.b64 rb, {%4, %5};\n\t"
        "mov.b64 rc, {%0, %1};\n\t"
        "fma.rn.f32x2 rc, ra, rb, rc;\n\t"
        "mov.b64 {%0, %1}, rc;\n\t"
        "}"
        : "+f"(c.x), "+f"(c.y)
        : "f"(a.x), "f"(a.y), "f"(b.x), "f"(b.y));
}

__device__ __forceinline__ uint32_t smem_u32(const void* p) {
    uint32_t a;
    asm("{ .reg .u64 t; cvta.to.shared.u64 t, %1; cvt.u32.u64 %0, t; }" : "=r"(a) : "l"(p));
    return a;
}

__device__ __forceinline__ void mma_f16(float d[4], const uint32_t a[4],
                                        uint32_t b0, uint32_t b1) {
    asm volatile(
        "mma.sync.aligned.m16n8k16.row.col.f32.f16.f16.f32 "
        "{%0,%1,%2,%3}, {%4,%5,%6,%7}, {%8,%9}, {%0,%1,%2,%3};"
        : "+f"(d[0]), "+f"(d[1]), "+f"(d[2]), "+f"(d[3])
        : "r"(a[0]), "r"(a[1]), "r"(a[2]), "r"(a[3]), "r"(b0), "r"(b1));
}

__device__ __forceinline__ void ldsm4(uint32_t* r, uint32_t addr) {
    asm volatile("ldmatrix.sync.aligned.m8n8.x4.shared.b16 {%0,%1,%2,%3}, [%4];"
                 : "=r"(r[0]), "=r"(r[1]), "=r"(r[2]), "=r"(r[3]) : "r"(addr));
}

__device__ __forceinline__ void cp16(uint32_t sdst, const void* gsrc) {
    asm volatile("cp.async.cg.shared.global [%0], [%1], 16;" :: "r"(sdst), "l"(gsrc));
}
__device__ __forceinline__ void cp_commit() {
    asm volatile("cp.async.commit_group;" ::: "memory");
}
template <int NW>
__device__ __forceinline__ void cp_wait() {
    asm volatile("cp.async.wait_group %0;" :: "n"(NW) : "memory");
}
__device__ __forceinline__ void cp_wait_ahead(int ahead) {
    if (ahead >= 2) cp_wait<2>();
    else if (ahead == 1) cp_wait<1>();
    else cp_wait<0>();
}

__device__ __forceinline__ void split_half(float x, __half& h, __half& l) {
    h = __float2half(x);
    l = __float2half(x - __half2float(h));
}

// grid-wide software barriers (monotonic counters; reset each replay in k_init)
__device__ __forceinline__ void gbar_on(unsigned* ctr, unsigned target) {
    __syncthreads();
    if (threadIdx.x == 0) {
        __threadfence();
        atomicAdd(ctr, 1u);
        unsigned v;
        do {
            asm volatile("ld.acquire.gpu.u32 %0, [%1];" : "=r"(v) : "l"(ctr));
        } while (v < target);
    }
    __syncthreads();
}

// ---------------------------------------------------------------------------
// init: P[1] = dA (hi/lo, natural + transposed), K[0] = dB, counters reset
// ---------------------------------------------------------------------------
__global__ void k_init(const float* __restrict__ dA, const float* __restrict__ dB) {
    int idx = blockIdx.x * 256 + threadIdx.x;
    if (idx == 0) { g_barctr = 0u; g_barctr2 = 0u; }
    if (idx < 256) g_tilecnt[idx] = 0u;
    if (idx < N_DIM * N_DIM) {
        int i = idx >> 8, j = idx & 255;
        float x = dA[idx];
        __half h, l;
        split_half(x, h, l);
        g_Pq[1][i][j] = h;
        g_Pl[1][i][j] = l;
        g_PqT[1][j][i] = h;
        g_PlT[1][j][i] = l;
    }
    if (idx < N_DIM) {
        g_K[0][idx] = dB[idx];
        g_KTq[idx][0] = __float2half(dB[idx]);
    }
}

// ---------------------------------------------------------------------------
// powerall v2: tensor-core fp16 3-split power chain (7 phases, split-K early),
// then tail: P256 fp32, Kvec (hi+lo reconstruct), PT fp32, shifted uR copies.
// Tile = 64x64, K-chunk 64, 2-buffer smem ring.
// smem layout per stage: AH(9216) AL(9216) BH(9216) BL(9216) = 36864; x2
// ---------------------------------------------------------------------------
#define PW_AL 9216
#define PW_BH 18432
#define PW_BL 27648
#define PW_STG 36864
#define PW_SMEM (2 * PW_STG + 1024)

__global__ void __launch_bounds__(256, 2) k_powerall(const float* __restrict__ dB,
                                                     const float* __restrict__ u) {
    extern __shared__ char pwsm[];
    const uint32_t sbp = smem_u32(pwsm);
    __shared__ unsigned s_old;
    int tid = threadIdx.x;
    const int lane = tid & 31, wid = tid >> 5;
    const int wm = wid & 1, wn = wid >> 1;   // 2 x 4 warps: tile M64 x N64

    // stage one K-chunk (64) of A = P[jA] rows, B = P[mB]^T rows (= g_PqT)
    auto stage_t = [&](int jA, int mB, int row0, int col0, int kc_abs, int buf) {
        uint32_t s0 = sbp + (uint32_t)buf * PW_STG;
        int k0 = kc_abs * 64;
#pragma unroll
        for (int it = 0; it < 2; it++) {
            int e = it * 256 + tid;
            int row = e >> 3, v = e & 7;
            cp16(s0 + row * 144 + v * 16, &g_Pq[jA][row0 + row][k0 + v * 8]);
            cp16(s0 + PW_AL + row * 144 + v * 16, &g_Pl[jA][row0 + row][k0 + v * 8]);
            cp16(s0 + PW_BH + row * 144 + v * 16, &g_PqT[mB][col0 + row][k0 + v * 8]);
            cp16(s0 + PW_BL + row * 144 + v * 16, &g_PlT[mB][col0 + row][k0 + v * 8]);
        }
        cp_commit();
    };

    auto compute_t = [&](int buf, float acc[2][2][4]) {
        uint32_t s0 = sbp + (uint32_t)buf * PW_STG;
        uint32_t aA = s0 + (wm * 32 + (lane & 15)) * 144 + (lane >> 4) * 16;
        uint32_t aB = s0 + PW_BH + (wn * 16 + (lane & 15)) * 144 + (lane >> 4) * 16;
#pragma unroll
        for (int ks = 0; ks < 4; ks++) {
            uint32_t Ah[8], Al[8];
#pragma unroll
            for (int ma = 0; ma < 2; ma++) {
                ldsm4(&Ah[ma * 4], aA + ma * (16 * 144) + ks * 32);
                ldsm4(&Al[ma * 4], aA + PW_AL + ma * (16 * 144) + ks * 32);
            }
            uint32_t bh[4], bl[4];
            ldsm4(bh, aB + ks * 32);
            ldsm4(bl, aB + (PW_BL - PW_BH) + ks * 32);
#pragma unroll
            for (int nb = 0; nb < 2; nb++) {
#pragma unroll
                for (int ma = 0; ma < 2; ma++) {
                    mma_f16(acc[ma][nb], &Ah[ma * 4], bh[nb], bh[2 + nb]);
                    mma_f16(acc[ma][nb], &Ah[ma * 4], bl[nb], bl[2 + nb]);
                    mma_f16(acc[ma][nb], &Al[ma * 4], bh[nb], bh[2 + nb]);
                }
            }
        }
    };

    auto tile_t = [&](int jA, int mB, int row0, int col0, int kc0, int nkc,
                      float acc[2][2][4]) {
#pragma unroll
        for (int ma = 0; ma < 2; ma++)
#pragma unroll
            for (int nb = 0; nb < 2; nb++)
#pragma unroll
                for (int q = 0; q < 4; q++) acc[ma][nb][q] = 0.f;
        stage_t(jA, mB, row0, col0, kc0, 0);
#pragma unroll 1
        for (int kc = 0; kc < nkc; kc++) {
            if (kc + 1 < nkc) {
                stage_t(jA, mB, row0, col0, kc0 + kc + 1, (kc + 1) & 1);
                cp_wait<1>();
            } else {
                cp_wait<0>();
            }
            __syncthreads();
            compute_t(kc & 1, acc);
            __syncthreads();
        }
    };

    // epilogue: write hi/lo natural + transposed (and nothing else)
    auto epi_full = [&](int d, int row0, int col0, float acc[2][2][4]) {
#pragma unroll
        for (int ma = 0; ma < 2; ma++) {
#pragma unroll
            for (int nb = 0; nb < 2; nb++) {
                int row = row0 + wm * 32 + ma * 16 + (lane >> 2);
                int col = col0 + wn * 16 + nb * 8 + (lane & 3) * 2;
#pragma unroll
                for (int h = 0; h < 2; h++) {
                    int rr = row + h * 8;
                    float v0 = acc[ma][nb][h * 2 + 0], v1 = acc[ma][nb][h * 2 + 1];
                    __half h0, l0, h1, l1;
                    split_half(v0, h0, l0);
                    split_half(v1, h1, l1);
                    g_Pq[d][rr][col] = h0;   g_Pq[d][rr][col + 1] = h1;
                    g_Pl[d][rr][col] = l0;   g_Pl[d][rr][col + 1] = l1;
                    g_PqT[d][col][rr] = h0;  g_PqT[d][col + 1][rr] = h1;
                    g_PlT[d][col][rr] = l0;  g_PlT[d][col + 1][rr] = l1;
                }
            }
        }
    };

    const int SPL[7] = {4, 4, 2, 2, 1, 1, 1};

    for (int ph = 0; ph < 7; ph++) {
        int m = 1 << ph;
        int sk = SPL[ph];
        int ntile = 16 * m;
        int nwork = ntile * sk;
        int nkc = 4 / sk;
        for (int w = blockIdx.x; w < nwork; w += PGRID) {
            int tile = w / sk, slice = w - tile * sk;
            int j = (tile >> 4) + 1, ti = tile & 15;
            int row0 = (ti >> 2) * 64, col0 = (ti & 3) * 64;
            float acc[2][2][4];
            tile_t(j, m, row0, col0, slice * nkc, nkc, acc);

            if (sk == 1) {
                epi_full(m + j, row0, col0, acc);
            } else {
                // write fp32 partial
#pragma unroll
                for (int ma = 0; ma < 2; ma++)
#pragma unroll
                    for (int nb = 0; nb < 2; nb++) {
                        int rl = wm * 32 + ma * 16 + (lane >> 2);
                        int cl = wn * 16 + nb * 8 + (lane & 3) * 2;
                        *reinterpret_cast<float2*>(&g_Ppart[w][rl * 64 + cl]) =
                            make_float2(acc[ma][nb][0], acc[ma][nb][1]);
                        *reinterpret_cast<float2*>(&g_Ppart[w][(rl + 8) * 64 + cl]) =
                            make_float2(acc[ma][nb][2], acc[ma][nb][3]);
                    }
                __syncthreads();
                if (tid == 0) {
                    __threadfence();
                    s_old = atomicAdd(&g_tilecnt[tile], 1u);
                }
                __syncthreads();
                if (s_old == (unsigned)(sk - 1)) {
                    // deterministic last-arriver reduction
                    int d = m + j;
#pragma unroll 1
                    for (int e = tid; e < 4096; e += 256) {
                        int rl = e >> 6, cl = e & 63;
                        float vs = 0.f;
                        for (int s2 = 0; s2 < sk; s2++)
                            vs += __ldcg(&g_Ppart[tile * sk + s2][e]);
                        __half h, l;
                        split_half(vs, h, l);
                        g_Pq[d][row0 + rl][col0 + cl] = h;
                        g_Pl[d][row0 + rl][col0 + cl] = l;
                        g_PqT[d][col0 + cl][row0 + rl] = h;
                        g_PlT[d][col0 + cl][row0 + rl] = l;
                    }
                    __syncthreads();
                    if (tid == 0) g_tilecnt[tile] = 0u;
                }
            }
        }
        gbar_on(&g_barctr, PGRID * (unsigned)(ph + 1));
    }

    // ---- tail (disjoint CTA ranges) ----
    int bx = blockIdx.x;
    if (bx < 16) {
        // P256 = P128 @ P128, fp32 output for the parity scan
        int row0 = (bx >> 2) * 64, col0 = (bx & 3) * 64;
        float acc[2][2][4];
        tile_t(CHK, CHK, row0, col0, 0, 4, acc);
#pragma unroll
        for (int ma = 0; ma < 2; ma++)
#pragma unroll
            for (int nb = 0; nb < 2; nb++) {
                int row = row0 + wm * 32 + ma * 16 + (lane >> 2);
                int col = col0 + wn * 16 + nb * 8 + (lane & 3) * 2;
                *reinterpret_cast<float2*>(&g_P2[row][col]) =
                    make_float2(acc[ma][nb][0], acc[ma][nb][1]);
                *reinterpret_cast<float2*>(&g_P2[row + 8][col]) =
                    make_float2(acc[ma][nb][2], acc[ma][nb][3]);
            }
    } else if (bx < 143) {
        // Kvec: K[k] = P[k] @ dB with P reconstructed hi+lo
        float* sDB = reinterpret_cast<float*>(pwsm + 2 * PW_STG);
        sDB[tid] = dB[tid];
        __syncthreads();
        int k = bx - 15;
        int i = tid;
        const __half2* rh = reinterpret_cast<const __half2*>(&g_Pq[k][i][0]);
        const __half2* rl = reinterpret_cast<const __half2*>(&g_Pl[k][i][0]);
        float acc = 0.0f;
#pragma unroll 8
        for (int jj = 0; jj < 128; jj++) {
            float2 ah = __half22float2(rh[jj]);
            float2 al = __half22float2(rl[jj]);
            acc += (ah.x + al.x) * sDB[2 * jj] + (ah.y + al.y) * sDB[2 * jj + 1];
        }
        g_K[k][i] = acc;
        g_KTq[i][k] = __float2half(acc);
    } else if (bx < 159) {
        // PT fp32: PT[k][i] = P128[i][k] = hi_T + lo_T elementwise
        int base = (bx - 143) * 4096 + tid * 16;
        const __half* hT = &g_PqT[CHK][0][0];
        const __half* lT = &g_PlT[CHK][0][0];
#pragma unroll
        for (int q = 0; q < 16; q++) {
            int e = base + q;
            (&g_PT[0][0])[e] = __half2float(hT[e]) + __half2float(lT[e]);
        }
    } else {
        // 8 shifted reversed-u fp16 copies
        const int total8 = 8 * NCHUNK * B_DIM * 256;
        for (int idx = (bx - 159) * 256 + tid; idx < total8;
             idx += (PGRID - 159) * 256) {
            int s = idx >> 19;
            int rem = idx & ((1 << 19) - 1);
            int c = rem >> 15;
            int b = (rem >> 8) & 127;
            int x = rem & 255;
            int q = x + s;
            float v = (q <= 127) ? u[(c * CHK + 127 - q) * B_DIM + b] : 0.0f;
            g_uRq8[s][c][b][x] = __float2half(v);
        }
    }
}

// ---------------------------------------------------------------------------
// k_post: etail + fprep + parity-scan fused in one launch (grid barriers).
// ---------------------------------------------------------------------------
#define POST_SMEM (256 * 34 * 4 + 32 * 260 * 4)

__global__ void __launch_bounds__(256, 1) k_post(const float* __restrict__ u) {
    extern __shared__ float sp[];
    int tid = threadIdx.x, tx = tid & 15, ty = tid >> 4;
    int bx = blockIdx.x;
    unsigned epoch = 0;

    // ================= phase 1: etail =================
    {
        int j = bx >> 3;
        int b0 = ((bx >> 2) & 1) * 64, i0 = (bx & 3) * 64;
        int t0 = j * CHK;
        float (*Ast)[16][68] = reinterpret_cast<float(*)[16][68]>(sp);
        float (*Bss)[16][68] = reinterpret_cast<float(*)[16][68]>(sp + 4 * 16 * 68);
        auto issue = [&](int kc) {
            int s = kc & 3, k0 = kc * 16;
            int kk = tid >> 4, v = tid & 15;
            cp16(smem_u32(&Ast[s][kk][v * 4]),
                 &u[(t0 + 127 - (k0 + kk)) * B_DIM + b0 + v * 4]);
            cp16(smem_u32(&Bss[s][kk][v * 4]), &g_K[k0 + kk][i0 + v * 4]);
            cp_commit();
        };
        issue(0); issue(1); issue(2);
        float2 acc[4][2] = {};
#pragma unroll 1
        for (int kc = 0; kc < 8; kc++) {
            cp_wait_ahead(7 - kc);
            __syncthreads();
            if (kc + 3 < 8) issue(kc + 3);
            int s = kc & 3;
#pragma unroll
            for (int kk = 0; kk < 16; kk++) {
                float2 b0v = *reinterpret_cast<const float2*>(&Bss[s][kk][tx * 4]);
                float2 b1v = *reinterpret_cast<const float2*>(&Bss[s][kk][tx * 4 + 2]);
#pragma unroll
                for (int ii = 0; ii < 4; ii++) {
                    float a = Ast[s][kk][ty * 4 + ii];
                    float2 a2 = make_float2(a, a);
                    ffma2(acc[ii][0], a2, b0v);
                    ffma2(acc[ii][1], a2, b1v);
                }
            }
        }
        __syncthreads();
#pragma unroll
        for (int ii = 0; ii < 4; ii++) {
            *reinterpret_cast<float4*>(&g_E[j][b0 + ty * 4 + ii][i0 + tx * 4]) =
                make_float4(acc[ii][0].x, acc[ii][0].y, acc[ii][1].x, acc[ii][1].y);
        }
    }
    gbar_on(&g_barctr2, POSTG * (++epoch));

    // ================= phase 2: fprep =================
    if (bx < 120) {
        int j = (bx >> 3) + 1;
        int b0 = ((bx >> 2) & 1) * 64, i0 = (bx & 3) * 64;
        const float* __restrict__ A = &g_E[j - 1][0][0];
        const float* __restrict__ B = &g_PT[0][0];
        float (*As)[64][20] = reinterpret_cast<float(*)[64][20]>(sp);
        float (*Bss)[16][68] = reinterpret_cast<float(*)[16][68]>(sp + 4 * 64 * 20);
        auto issue = [&](int kc) {
            int s = kc & 3, k0 = kc * 16;
            {
                int row = tid >> 2, v = tid & 3;
                cp16(smem_u32(&As[s][row][v * 4]), &A[(b0 + row) * N_DIM + k0 + v * 4]);
            }
            {
                int row = tid >> 4, v = tid & 15;
                cp16(smem_u32(&Bss[s][row][v * 4]), &B[(k0 + row) * N_DIM + i0 + v * 4]);
            }
            cp_commit();
        };
        issue(0); issue(1); issue(2);
        float2 acc[4][2] = {};
#pragma unroll 1
        for (int kc = 0; kc < 16; kc++) {
            cp_wait_ahead(15 - kc);
            __syncthreads();
            if (kc + 3 < 16) issue(kc + 3);
            int s = kc & 3;
#pragma unroll
            for (int kk4 = 0; kk4 < 4; kk4++) {
                float4 a4[4];
#pragma unroll
                for (int ii = 0; ii < 4; ii++)
                    a4[ii] = *reinterpret_cast<const float4*>(&As[s][ty * 4 + ii][kk4 * 4]);
#pragma unroll
                for (int q = 0; q < 4; q++) {
                    int kk = kk4 * 4 + q;
                    float2 b0v = *reinterpret_cast<const float2*>(&Bss[s][kk][tx * 4]);
                    float2 b1v = *reinterpret_cast<const float2*>(&Bss[s][kk][tx * 4 + 2]);
#pragma unroll
                    for (int ii = 0; ii < 4; ii++) {
                        float av = (q == 0) ? a4[ii].x : (q == 1) ? a4[ii].y
                                 : (q == 2) ? a4[ii].z : a4[ii].w;
                        float2 a2 = make_float2(av, av);
                        ffma2(acc[ii][0], a2, b0v);
                        ffma2(acc[ii][1], a2, b1v);
                    }
                }
            }
        }
        __syncthreads();
#pragma unroll
        for (int ii = 0; ii < 4; ii++) {
            int b = b0 + ty * 4 + ii;
            float4 e = *reinterpret_cast<const float4*>(&g_E[j][b][i0 + tx * 4]);
            *reinterpret_cast<float4*>(&g_F[j][b][i0 + tx * 4]) =
                make_float4(e.x + acc[ii][0].x, e.y + acc[ii][0].y,
                            e.z + acc[ii][1].x, e.w + acc[ii][1].y);
        }
    }
    gbar_on(&g_barctr2, POSTG * (++epoch));

    // ================= phase 3: parity scan =================
    {
        bool sact = bx < 64;
        int par = bx & 1, tb = bx >> 1;
        int b0 = (tb >> 3) * 32, i0 = (tb & 7) * 32;
        float (*Psm)[34] = reinterpret_cast<float(*)[34]>(sp);
        float (*Xs)[260] = reinterpret_cast<float(*)[260]>(sp + 256 * 34);

        if (sact) {
#pragma unroll
            for (int it = 0; it < 8; it++) {
                int e = it * 256 + tid;
                int ir = e >> 6, v = e & 63;
                float4 x = *reinterpret_cast<const float4*>(&g_P2[i0 + ir][v * 4]);
                Psm[v * 4 + 0][ir] = x.x;
                Psm[v * 4 + 1][ir] = x.y;
                Psm[v * 4 + 2][ir] = x.z;
                Psm[v * 4 + 3][ir] = x.w;
            }
            int r = tid >> 3, v = tid & 7;
            const float* src = (par == 0) ? &g_E[0][0][0] : &g_F[1][0][0];
            float4 x0 = *reinterpret_cast<const float4*>(src + (b0 + r) * N_DIM + i0 + v * 4);
            *reinterpret_cast<float4*>(&g_Xf[par][0][b0 + r][i0 + v * 4]) = x0;
            *reinterpret_cast<__half2*>(&g_Xq[1 + par][b0 + r][i0 + v * 4]) =
                __floats2half2_rn(x0.x, x0.y);
            *reinterpret_cast<__half2*>(&g_Xq[1 + par][b0 + r][i0 + v * 4 + 2]) =
                __floats2half2_rn(x0.z, x0.w);
        }
        gbar_on(&g_barctr2, POSTG * (++epoch));

        int ty2 = tid >> 3, tx2 = tid & 7;
        for (int s = 1; s <= 7; s++) {
            int j = 2 * s + par;
            bool active = sact && ((par == 0) ? (s <= 7) : (s <= 6));
            if (active) {
                const float* src = &g_Xf[par][(s - 1) & 1][0][0];
#pragma unroll
                for (int it = 0; it < 8; it++) {
                    int e = it * 256 + tid;
                    int r = e >> 6, v = e & 63;
                    float4 x = *reinterpret_cast<const float4*>(src + (b0 + r) * N_DIM + v * 4);
                    *reinterpret_cast<float4*>(&Xs[r][v * 4]) = x;
                }
                __syncthreads();
                float2 c0 = make_float2(0.f, 0.f), c1 = make_float2(0.f, 0.f);
#pragma unroll 4
                for (int k = 0; k < 256; k++) {
                    float2 p0 = *reinterpret_cast<const float2*>(&Psm[k][tx2 * 4]);
                    float2 p1 = *reinterpret_cast<const float2*>(&Psm[k][tx2 * 4 + 2]);
                    float a = Xs[ty2][k];
                    float2 a2 = make_float2(a, a);
                    ffma2(c0, a2, p0);
                    ffma2(c1, a2, p1);
                }
                float4 fj = *reinterpret_cast<const float4*>(&g_F[j][b0 + ty2][i0 + tx2 * 4]);
                float4 xv = make_float4(fj.x + c0.x, fj.y + c0.y, fj.z + c1.x, fj.w + c1.y);
                *reinterpret_cast<float4*>(&g_Xf[par][s & 1][b0 + ty2][i0 + tx2 * 4]) = xv;
                *reinterpret_cast<__half2*>(&g_Xq[j + 1][b0 + ty2][i0 + tx2 * 4]) =
                    __floats2half2_rn(xv.x, xv.y);
                *reinterpret_cast<__half2*>(&g_Xq[j + 1][b0 + ty2][i0 + tx2 * 4 + 2]) =
                    __floats2half2_rn(xv.z, xv.w);
            }
            gbar_on(&g_barctr2, POSTG * (++epoch));
        }
    }
}

// ---------------------------------------------------------------------------
// fused mma kernel v7: non-persistent (grid 4096) with PAIR-UNROLLED chunks:
// 4-buffer ring, constant cp_wait<2> per pair, empty groups always committed.
// fp16 single product, zero-chunk skip, evict-first stores.
// ---------------------------------------------------------------------------
#define FST 80          // smem row stride bytes (32 fp16 = 64B + 16 pad)
#define ST_B 10240
#define STAGE_B 20480
#define SMEM_FUSED (4 * STAGE_B)

__global__ void __launch_bounds__(256, 2) k_fused(float* __restrict__ out) {
    extern __shared__ char smbuf[];
    const uint32_t sb = smem_u32(smbuf);
    const int tid = threadIdx.x;
    const int lane = tid & 31, wid = tid >> 5;
    const int wm = wid & 3, wn = wid >> 2;        // 4 x 2 warp grid
    const int bx = blockIdx.x;
    const int r = bx >> 5;                        // 32 consecutive CTAs share P[r+1]
    const int c = (bx >> 1) & 15;
    const int bn = bx & 1;                        // N-half
    const int t = c * CHK + r;

    float acc[2][8][4];
#pragma unroll
    for (int ma = 0; ma < 2; ma++)
#pragma unroll
        for (int nb = 0; nb < 8; nb++)
#pragma unroll
            for (int q = 0; q < 4; q++) acc[ma][nb][q] = 0.f;

    const int nc = (r >> 5) + 1;                  // conv chunks
    const int nact = nc + ((c > 0) ? 8 : 0);      // + X chunks
    const int s8 = (127 - r) & 7;
    const int xbase = 127 - r - s8;               // 8-aligned

    // stage chunk li into buffer li&3; ALWAYS commits (empty group if li>=nact)
    auto stage = [&](int li) {
        if (li < nact) {
            int kc = (li < nc) ? li : (li - nc + 4);
            uint32_t s0 = sb + (uint32_t)(li & 3) * STAGE_B;
            if (kc < 4) {
                int x0 = xbase + kc * 32;
#pragma unroll
                for (int it = 0; it < 2; it++) {
                    int e = it * 256 + tid;
                    int row = e >> 2, v = e & 3;
                    cp16(s0 + row * FST + v * 16, &g_uRq8[s8][c][row][x0 + v * 8]);
                }
#pragma unroll
                for (int it = 0; it < 2; it++) {
                    int e = it * 256 + tid;
                    int row = e >> 2, v = e & 3;
                    cp16(s0 + ST_B + row * FST + v * 16,
                         &g_KTq[bn * 128 + row][kc * 32 + v * 8]);
                }
            } else {
                int kb = (kc - 4) * 32;
#pragma unroll
                for (int it = 0; it < 2; it++) {
                    int e = it * 256 + tid;
                    int row = e >> 2, v = e & 3;
                    cp16(s0 + row * FST + v * 16, &g_Xq[c][row][kb + v * 8]);
                }
#pragma unroll
                for (int it = 0; it < 2; it++) {
                    int e = it * 256 + tid;
                    int row = e >> 2, v = e & 3;
                    cp16(s0 + ST_B + row * FST + v * 16,
                         &g_Pq[r + 1][bn * 128 + row][kb + v * 8]);
                }
            }
        }
        cp_commit();
    };

    auto compute = [&](int buf) {
        uint32_t s0 = sb + (uint32_t)buf * STAGE_B;
        uint32_t aA = s0 + (wm * 32 + (lane & 15)) * FST + (lane >> 4) * 16;
        uint32_t aB = s0 + ST_B + (wn * 64 + (lane & 15)) * FST + (lane >> 4) * 16;
#pragma unroll
        for (int ks = 0; ks < 2; ks++) {
            uint32_t Ah[8];
#pragma unroll
            for (int ma = 0; ma < 2; ma++)
                ldsm4(&Ah[ma * 4], aA + ma * (16 * FST) + ks * 32);
#pragma unroll
            for (int pr = 0; pr < 4; pr++) {
                uint32_t bh[4];
                ldsm4(bh, aB + pr * (16 * FST) + ks * 32);
#pragma unroll
                for (int sub = 0; sub < 2; sub++) {
                    int nb = pr * 2 + sub;
#pragma unroll
                    for (int ma = 0; ma < 2; ma++)
                        mma_f16(acc[ma][nb], &Ah[ma * 4], bh[sub], bh[2 + sub]);
                }
            }
        }
    };

    // prefill 4 groups (some possibly empty)
    stage(0); stage(1); stage(2); stage(3);

    int li = 0;
#pragma unroll 1
    while (li + 1 < nact) {
        cp_wait<2>();
        __syncthreads();
        compute(li & 3);
        compute((li + 1) & 3);
        __syncthreads();
        stage(li + 4);
        stage(li + 5);
        li += 2;
    }
    if (li < nact) {
        cp_wait<0>();
        __syncthreads();
        compute(li & 3);
    }

    // epilogue: evict-first fp32 stores
    float* outt = out + (size_t)t * (B_DIM * N_DIM);
#pragma unroll
    for (int ma = 0; ma < 2; ma++) {
        int row = wm * 32 + ma * 16 + (lane >> 2);
#pragma unroll
        for (int nb = 0; nb < 8; nb++) {
            int col = bn * 128 + wn * 64 + nb * 8 + (lane & 3) * 2;
            __stcs(reinterpret_cast<float2*>(outt + row * 256 + col),
                   make_float2(acc[ma][nb][0], acc[ma][nb][1]));
            __stcs(reinterpret_cast<float2*>(outt + (row + 8) * 256 + col),
                   make_float2(acc[ma][nb][2], acc[ma][nb][3]));
        }
    }
}

// ---------------------------------------------------------------------------
extern "C" void kernel_launch(void* const* d_in, const int* in_sizes, int n_in,
                              void* d_out, int out_size) {
    const float* u  = (const float*)d_in[0];   // [L, B]
    const float* dA = (const float*)d_in[1];   // [N, N]
    const float* dB = (const float*)d_in[2];   // [N]
    float* out = (float*)d_out;                // [L, B, N]

    cudaFuncSetAttribute(k_fused, cudaFuncAttributeMaxDynamicSharedMemorySize, SMEM_FUSED);
    cudaFuncSetAttribute(k_post, cudaFuncAttributeMaxDynamicSharedMemorySize, POST_SMEM);
    cudaFuncSetAttribute(k_powerall, cudaFuncAttributeMaxDynamicSharedMemorySize, PW_SMEM);

    k_init<<<256, 256>>>(dA, dB);
    k_powerall<<<PGRID, 256, PW_SMEM>>>(dB, u);
    k_post<<<POSTG, 256, POST_SMEM>>>(u);
    k_fused<<<2 * L_DIM, 256, SMEM_FUSED>>>(out);
}

// round 13
// speedup vs baseline: 1.1014x; 1.1014x over previous
#include <cuda_runtime.h>
#include <cuda_fp16.h>
#include <cstdint>

// Problem constants
#define N_DIM 256
#define L_DIM 2048
#define B_DIM 128
#define CHK   128
#define NCHUNK 16
#define PGRID 296
#define POSTG 128

// ---------------------------------------------------------------------------
// Device global scratch
// ---------------------------------------------------------------------------
__device__ float g_P[CHK + 1][N_DIM][N_DIM];        // dA^p fp32, p = 1..128
__device__ float g_P2[N_DIM][N_DIM];                // dA^256 fp32 (T^2)
__device__ float g_PT[N_DIM][N_DIM];                // P128^T fp32
__device__ float g_K[CHK][N_DIM];                   // Kvec fp32
__device__ float g_E[NCHUNK][B_DIM][N_DIM];         // chunk-end conv values
__device__ float g_F[NCHUNK][B_DIM][N_DIM];         // F_j = E_j + E_{j-1} T
__device__ float g_Xf[2][2][B_DIM][N_DIM];          // fp32 X ping-pong per parity
__device__ float g_Ppart[256][4096];                // split-K partial tiles
__device__ unsigned g_tilecnt[256];                 // split-K arrival counters
__device__ __half g_Pq[CHK + 1][N_DIM][N_DIM];      // fp16 P
__device__ __half g_KTq[N_DIM][CHK];                // fp16 K transposed
__device__ __half g_uRq8[8][NCHUNK][B_DIM][256];    // 8 byte-shift copies of reversed u
__device__ __half g_Xq[NCHUNK][B_DIM][N_DIM];       // fp16 X_{c-1} (c>=1)
__device__ unsigned g_barctr;
__device__ unsigned g_barctr2;

// ---------------------------------------------------------------------------
// helpers
// ---------------------------------------------------------------------------
__device__ __forceinline__ void ffma2(float2& c, float2 a, float2 b) {
    asm("{\n\t"
        ".reg .b64 ra, rb, rc;\n\t"
        "mov.b64 ra, {%2, %3};\n\t"
        "mov.b64 rb, {%4, %5};\n\t"
        "mov.b64 rc, {%0, %1};\n\t"
        "fma.rn.f32x2 rc, ra, rb, rc;\n\t"
        "mov.b64 {%0, %1}, rc;\n\t"
        "}"
        : "+f"(c.x), "+f"(c.y)
        : "f"(a.x), "f"(a.y), "f"(b.x), "f"(b.y));
}

__device__ __forceinline__ uint32_t smem_u32(const void* p) {
    uint32_t a;
    asm("{ .reg .u64 t; cvta.to.shared.u64 t, %1; cvt.u32.u64 %0, t; }" : "=r"(a) : "l"(p));
    return a;
}

__device__ __forceinline__ void mma_f16(float d[4], const uint32_t a[4],
                                        uint32_t b0, uint32_t b1) {
    asm volatile(
        "mma.sync.aligned.m16n8k16.row.col.f32.f16.f16.f32 "
        "{%0,%1,%2,%3}, {%4,%5,%6,%7}, {%8,%9}, {%0,%1,%2,%3};"
        : "+f"(d[0]), "+f"(d[1]), "+f"(d[2]), "+f"(d[3])
        : "r"(a[0]), "r"(a[1]), "r"(a[2]), "r"(a[3]), "r"(b0), "r"(b1));
}

__device__ __forceinline__ void ldsm4(uint32_t* r, uint32_t addr) {
    asm volatile("ldmatrix.sync.aligned.m8n8.x4.shared.b16 {%0,%1,%2,%3}, [%4];"
                 : "=r"(r[0]), "=r"(r[1]), "=r"(r[2]), "=r"(r[3]) : "r"(addr));
}

__device__ __forceinline__ void cp16(uint32_t sdst, const void* gsrc) {
    asm volatile("cp.async.cg.shared.global [%0], [%1], 16;" :: "r"(sdst), "l"(gsrc));
}
__device__ __forceinline__ void cp_commit() {
    asm volatile("cp.async.commit_group;" ::: "memory");
}
template <int NW>
__device__ __forceinline__ void cp_wait() {
    asm volatile("cp.async.wait_group %0;" :: "n"(NW) : "memory");
}
__device__ __forceinline__ void cp_wait_ahead(int ahead) {
    if (ahead >= 2) cp_wait<2>();
    else if (ahead == 1) cp_wait<1>();
    else cp_wait<0>();
}

// grid-wide software barriers (monotonic counters; reset each replay in k_init)
__device__ __forceinline__ void gbar_on(unsigned* ctr, unsigned target) {
    __syncthreads();
    if (threadIdx.x == 0) {
        __threadfence();
        atomicAdd(ctr, 1u);
        unsigned v;
        do {
            asm volatile("ld.acquire.gpu.u32 %0, [%1];" : "=r"(v) : "l"(ctr));
        } while (v < target);
    }
    __syncthreads();
}

// ---------------------------------------------------------------------------
// init: P[1] = dA (+ fp16), K[0] = dB, counters reset
// ---------------------------------------------------------------------------
__global__ void k_init(const float* __restrict__ dA, const float* __restrict__ dB) {
    int idx = blockIdx.x * 256 + threadIdx.x;
    if (idx == 0) { g_barctr = 0u; g_barctr2 = 0u; }
    if (idx < 256) g_tilecnt[idx] = 0u;
    if (idx < N_DIM * N_DIM) {
        float x = dA[idx];
        (&g_P[1][0][0])[idx] = x;
        (&g_Pq[1][0][0])[idx] = __float2half(x);
    }
    if (idx < N_DIM) {
        g_K[0][idx] = dB[idx];
        g_KTq[idx][0] = __float2half(dB[idx]);
    }
}

// ---------------------------------------------------------------------------
// single-launch power chain with split-K on early phases; tail computes
// P256, P128^T, Kvec (fp32 + fp16T), and 8 shifted reversed-u fp16 copies.
// ---------------------------------------------------------------------------
__global__ void __launch_bounds__(256, 2) k_powerall(const float* __restrict__ dB,
                                                     const float* __restrict__ u) {
    __shared__ __align__(16) float As[4][64][20];
    __shared__ __align__(16) float Bs[4][16][68];
    __shared__ unsigned s_old;
    int tid = threadIdx.x, tx = tid & 15, ty = tid >> 4;

    auto run_tile = [&](const float* __restrict__ A, const float* __restrict__ B,
                        int row0, int col0, int ks0, int nks, float2 acc[4][2]) {
        auto issue = [&](int kc) {
            int s = kc & 3, k0 = (ks0 + kc) * 16;
            {
                int row = tid >> 2, v = tid & 3;
                cp16(smem_u32(&As[s][row][v * 4]), &A[(row0 + row) * N_DIM + k0 + v * 4]);
            }
            {
                int row = tid >> 4, v = tid & 15;
                cp16(smem_u32(&Bs[s][row][v * 4]), &B[(k0 + row) * N_DIM + col0 + v * 4]);
            }
            cp_commit();
        };
#pragma unroll 1
        for (int p = 0; p < 3 && p < nks; p++) issue(p);
#pragma unroll 1
        for (int kc = 0; kc < nks; kc++) {
            cp_wait_ahead(nks - 1 - kc);
            __syncthreads();
            if (kc + 3 < nks) issue(kc + 3);
            int s = kc & 3;
#pragma unroll
            for (int kk4 = 0; kk4 < 4; kk4++) {
                float4 a4[4];
#pragma unroll
                for (int ii = 0; ii < 4; ii++)
                    a4[ii] = *reinterpret_cast<const float4*>(&As[s][ty * 4 + ii][kk4 * 4]);
#pragma unroll
                for (int q = 0; q < 4; q++) {
                    int kk = kk4 * 4 + q;
                    float2 b0 = *reinterpret_cast<const float2*>(&Bs[s][kk][tx * 4]);
                    float2 b1 = *reinterpret_cast<const float2*>(&Bs[s][kk][tx * 4 + 2]);
#pragma unroll
                    for (int ii = 0; ii < 4; ii++) {
                        float av = (q == 0) ? a4[ii].x : (q == 1) ? a4[ii].y
                                 : (q == 2) ? a4[ii].z : a4[ii].w;
                        float2 a2 = make_float2(av, av);
                        ffma2(acc[ii][0], a2, b0);
                        ffma2(acc[ii][1], a2, b1);
                    }
                }
            }
        }
        __syncthreads();
    };

    const int SPL[7] = {8, 8, 4, 2, 1, 1, 1};

    for (int ph = 0; ph < 7; ph++) {
        int m = 1 << ph;
        int sk = SPL[ph];
        int ntile = 16 * m;
        int nwork = ntile * sk;
        int nks = 16 / sk;
        for (int w = blockIdx.x; w < nwork; w += PGRID) {
            int tile = w / sk, slice = w - tile * sk;
            int j = (tile >> 4) + 1, ti = tile & 15;
            int row0 = (ti >> 2) * 64, col0 = (ti & 3) * 64;
            float2 acc[4][2] = {};
            run_tile(&g_P[j][0][0], &g_P[m][0][0], row0, col0, slice * nks, nks, acc);

            if (sk == 1) {
                float* C = &g_P[m + j][0][0];
                __half* Cq = &g_Pq[m + j][0][0];
#pragma unroll
                for (int ii = 0; ii < 4; ii++) {
                    int row = row0 + ty * 4 + ii, col = col0 + tx * 4;
                    float4 v = make_float4(acc[ii][0].x, acc[ii][0].y,
                                           acc[ii][1].x, acc[ii][1].y);
                    *reinterpret_cast<float4*>(&C[row * N_DIM + col]) = v;
                    *reinterpret_cast<__half2*>(&Cq[row * N_DIM + col]) =
                        __floats2half2_rn(v.x, v.y);
                    *reinterpret_cast<__half2*>(&Cq[row * N_DIM + col + 2]) =
                        __floats2half2_rn(v.z, v.w);
                }
            } else {
#pragma unroll
                for (int ii = 0; ii < 4; ii++) {
                    float4 v = make_float4(acc[ii][0].x, acc[ii][0].y,
                                           acc[ii][1].x, acc[ii][1].y);
                    *reinterpret_cast<float4*>(&g_Ppart[w][(ty * 4 + ii) * 64 + tx * 4]) = v;
                }
                __syncthreads();
                if (tid == 0) {
                    __threadfence();
                    s_old = atomicAdd(&g_tilecnt[tile], 1u);
                }
                __syncthreads();
                if (s_old == (unsigned)(sk - 1)) {
                    float* C = &g_P[m + j][0][0];
                    __half* Cq = &g_Pq[m + j][0][0];
#pragma unroll
                    for (int ii = 0; ii < 4; ii++) {
                        float4 vs = make_float4(0.f, 0.f, 0.f, 0.f);
                        for (int s2 = 0; s2 < sk; s2++) {
                            float4 pv = __ldcg(reinterpret_cast<const float4*>(
                                &g_Ppart[tile * sk + s2][(ty * 4 + ii) * 64 + tx * 4]));
                            vs.x += pv.x; vs.y += pv.y; vs.z += pv.z; vs.w += pv.w;
                        }
                        int row = row0 + ty * 4 + ii, col = col0 + tx * 4;
                        *reinterpret_cast<float4*>(&C[row * N_DIM + col]) = vs;
                        *reinterpret_cast<__half2*>(&Cq[row * N_DIM + col]) =
                            __floats2half2_rn(vs.x, vs.y);
                        *reinterpret_cast<__half2*>(&Cq[row * N_DIM + col + 2]) =
                            __floats2half2_rn(vs.z, vs.w);
                    }
                    __syncthreads();
                    if (tid == 0) g_tilecnt[tile] = 0u;
                }
            }
        }
        gbar_on(&g_barctr, PGRID * (unsigned)(ph + 1));
    }

    // ---- tail (disjoint CTA ranges) ----
    int bx = blockIdx.x;
    if (bx < 16) {
        int row0 = (bx >> 2) * 64, col0 = (bx & 3) * 64;
        float2 acc[4][2] = {};
        run_tile(&g_P[CHK][0][0], &g_P[CHK][0][0], row0, col0, 0, 16, acc);
#pragma unroll
        for (int ii = 0; ii < 4; ii++) {
            int row = row0 + ty * 4 + ii, col = col0 + tx * 4;
            *reinterpret_cast<float4*>(&g_P2[row][col]) =
                make_float4(acc[ii][0].x, acc[ii][0].y, acc[ii][1].x, acc[ii][1].y);
        }
    } else if (bx < 143) {
        float* sDB = &As[0][0][0];
        sDB[tid] = dB[tid];
        __syncthreads();
        int k = bx - 15;
        int i = tid;
        const float4* row4 = reinterpret_cast<const float4*>(&g_P[k][i][0]);
        const float4* sb4 = reinterpret_cast<const float4*>(sDB);
        float acc = 0.0f;
#pragma unroll 8
        for (int jj = 0; jj < N_DIM / 4; jj++) {
            float4 a = __ldcg(&row4[jj]);
            float4 b = sb4[jj];
            acc += a.x * b.x + a.y * b.y + a.z * b.z + a.w * b.w;
        }
        g_K[k][i] = acc;
        g_KTq[i][k] = __float2half(acc);
    } else if (bx < 159) {
        int base = (bx - 143) * 4096 + tid * 16;
        for (int q = 0; q < 16; q++) {
            int e = base + q;
            int k = e >> 8, i = e & 255;
            (&g_PT[0][0])[e] = __ldcg(&g_P[CHK][i][k]);
        }
    } else {
        const int total8 = 8 * NCHUNK * B_DIM * 256;
        for (int idx = (bx - 159) * 256 + tid; idx < total8;
             idx += (PGRID - 159) * 256) {
            int s = idx >> 19;
            int rem = idx & ((1 << 19) - 1);
            int c = rem >> 15;
            int b = (rem >> 8) & 127;
            int x = rem & 255;
            int q = x + s;
            float v = (q <= 127) ? u[(c * CHK + 127 - q) * B_DIM + b] : 0.0f;
            g_uRq8[s][c][b][x] = __float2half(v);
        }
    }
}

// ---------------------------------------------------------------------------
// k_post: etail + fprep + parity-scan fused in one launch (grid barriers).
// ---------------------------------------------------------------------------
#define POST_SMEM (256 * 34 * 4 + 32 * 260 * 4)

__global__ void __launch_bounds__(256, 1) k_post(const float* __restrict__ u) {
    extern __shared__ float sp[];
    int tid = threadIdx.x, tx = tid & 15, ty = tid >> 4;
    int bx = blockIdx.x;
    unsigned epoch = 0;

    // ================= phase 1: etail =================
    {
        int j = bx >> 3;
        int b0 = ((bx >> 2) & 1) * 64, i0 = (bx & 3) * 64;
        int t0 = j * CHK;
        float (*Ast)[16][68] = reinterpret_cast<float(*)[16][68]>(sp);
        float (*Bss)[16][68] = reinterpret_cast<float(*)[16][68]>(sp + 4 * 16 * 68);
        auto issue = [&](int kc) {
            int s = kc & 3, k0 = kc * 16;
            int kk = tid >> 4, v = tid & 15;
            cp16(smem_u32(&Ast[s][kk][v * 4]),
                 &u[(t0 + 127 - (k0 + kk)) * B_DIM + b0 + v * 4]);
            cp16(smem_u32(&Bss[s][kk][v * 4]), &g_K[k0 + kk][i0 + v * 4]);
            cp_commit();
        };
        issue(0); issue(1); issue(2);
        float2 acc[4][2] = {};
#pragma unroll 1
        for (int kc = 0; kc < 8; kc++) {
            cp_wait_ahead(7 - kc);
            __syncthreads();
            if (kc + 3 < 8) issue(kc + 3);
            int s = kc & 3;
#pragma unroll
            for (int kk = 0; kk < 16; kk++) {
                float2 b0v = *reinterpret_cast<const float2*>(&Bss[s][kk][tx * 4]);
                float2 b1v = *reinterpret_cast<const float2*>(&Bss[s][kk][tx * 4 + 2]);
#pragma unroll
                for (int ii = 0; ii < 4; ii++) {
                    float a = Ast[s][kk][ty * 4 + ii];
                    float2 a2 = make_float2(a, a);
                    ffma2(acc[ii][0], a2, b0v);
                    ffma2(acc[ii][1], a2, b1v);
                }
            }
        }
        __syncthreads();
#pragma unroll
        for (int ii = 0; ii < 4; ii++) {
            *reinterpret_cast<float4*>(&g_E[j][b0 + ty * 4 + ii][i0 + tx * 4]) =
                make_float4(acc[ii][0].x, acc[ii][0].y, acc[ii][1].x, acc[ii][1].y);
        }
    }
    gbar_on(&g_barctr2, POSTG * (++epoch));

    // ================= phase 2: fprep =================
    if (bx < 120) {
        int j = (bx >> 3) + 1;
        int b0 = ((bx >> 2) & 1) * 64, i0 = (bx & 3) * 64;
        const float* __restrict__ A = &g_E[j - 1][0][0];
        const float* __restrict__ B = &g_PT[0][0];
        float (*As)[64][20] = reinterpret_cast<float(*)[64][20]>(sp);
        float (*Bss)[16][68] = reinterpret_cast<float(*)[16][68]>(sp + 4 * 64 * 20);
        auto issue = [&](int kc) {
            int s = kc & 3, k0 = kc * 16;
            {
                int row = tid >> 2, v = tid & 3;
                cp16(smem_u32(&As[s][row][v * 4]), &A[(b0 + row) * N_DIM + k0 + v * 4]);
            }
            {
                int row = tid >> 4, v = tid & 15;
                cp16(smem_u32(&Bss[s][row][v * 4]), &B[(k0 + row) * N_DIM + i0 + v * 4]);
            }
            cp_commit();
        };
        issue(0); issue(1); issue(2);
        float2 acc[4][2] = {};
#pragma unroll 1
        for (int kc = 0; kc < 16; kc++) {
            cp_wait_ahead(15 - kc);
            __syncthreads();
            if (kc + 3 < 16) issue(kc + 3);
            int s = kc & 3;
#pragma unroll
            for (int kk4 = 0; kk4 < 4; kk4++) {
                float4 a4[4];
#pragma unroll
                for (int ii = 0; ii < 4; ii++)
                    a4[ii] = *reinterpret_cast<const float4*>(&As[s][ty * 4 + ii][kk4 * 4]);
#pragma unroll
                for (int q = 0; q < 4; q++) {
                    int kk = kk4 * 4 + q;
                    float2 b0v = *reinterpret_cast<const float2*>(&Bss[s][kk][tx * 4]);
                    float2 b1v = *reinterpret_cast<const float2*>(&Bss[s][kk][tx * 4 + 2]);
#pragma unroll
                    for (int ii = 0; ii < 4; ii++) {
                        float av = (q == 0) ? a4[ii].x : (q == 1) ? a4[ii].y
                                 : (q == 2) ? a4[ii].z : a4[ii].w;
                        float2 a2 = make_float2(av, av);
                        ffma2(acc[ii][0], a2, b0v);
                        ffma2(acc[ii][1], a2, b1v);
                    }
                }
            }
        }
        __syncthreads();
#pragma unroll
        for (int ii = 0; ii < 4; ii++) {
            int b = b0 + ty * 4 + ii;
            float4 e = *reinterpret_cast<const float4*>(&g_E[j][b][i0 + tx * 4]);
            *reinterpret_cast<float4*>(&g_F[j][b][i0 + tx * 4]) =
                make_float4(e.x + acc[ii][0].x, e.y + acc[ii][0].y,
                            e.z + acc[ii][1].x, e.w + acc[ii][1].y);
        }
    }
    gbar_on(&g_barctr2, POSTG * (++epoch));

    // ================= phase 3: parity scan =================
    {
        bool sact = bx < 64;
        int par = bx & 1, tb = bx >> 1;
        int b0 = (tb >> 3) * 32, i0 = (tb & 7) * 32;
        float (*Psm)[34] = reinterpret_cast<float(*)[34]>(sp);
        float (*Xs)[260] = reinterpret_cast<float(*)[260]>(sp + 256 * 34);

        if (sact) {
#pragma unroll
            for (int it = 0; it < 8; it++) {
                int e = it * 256 + tid;
                int ir = e >> 6, v = e & 63;
                float4 x = *reinterpret_cast<const float4*>(&g_P2[i0 + ir][v * 4]);
                Psm[v * 4 + 0][ir] = x.x;
                Psm[v * 4 + 1][ir] = x.y;
                Psm[v * 4 + 2][ir] = x.z;
                Psm[v * 4 + 3][ir] = x.w;
            }
            int r = tid >> 3, v = tid & 7;
            const float* src = (par == 0) ? &g_E[0][0][0] : &g_F[1][0][0];
            float4 x0 = *reinterpret_cast<const float4*>(src + (b0 + r) * N_DIM + i0 + v * 4);
            *reinterpret_cast<float4*>(&g_Xf[par][0][b0 + r][i0 + v * 4]) = x0;
            *reinterpret_cast<__half2*>(&g_Xq[1 + par][b0 + r][i0 + v * 4]) =
                __floats2half2_rn(x0.x, x0.y);
            *reinterpret_cast<__half2*>(&g_Xq[1 + par][b0 + r][i0 + v * 4 + 2]) =
                __floats2half2_rn(x0.z, x0.w);
        }
        gbar_on(&g_barctr2, POSTG * (++epoch));

        int ty2 = tid >> 3, tx2 = tid & 7;
        for (int s = 1; s <= 7; s++) {
            int j = 2 * s + par;
            bool active = sact && ((par == 0) ? (s <= 7) : (s <= 6));
            if (active) {
                const float* src = &g_Xf[par][(s - 1) & 1][0][0];
#pragma unroll
                for (int it = 0; it < 8; it++) {
                    int e = it * 256 + tid;
                    int r = e >> 6, v = e & 63;
                    float4 x = *reinterpret_cast<const float4*>(src + (b0 + r) * N_DIM + v * 4);
                    *reinterpret_cast<float4*>(&Xs[r][v * 4]) = x;
                }
                __syncthreads();
                float2 c0 = make_float2(0.f, 0.f), c1 = make_float2(0.f, 0.f);
#pragma unroll 4
                for (int k = 0; k < 256; k++) {
                    float2 p0 = *reinterpret_cast<const float2*>(&Psm[k][tx2 * 4]);
                    float2 p1 = *reinterpret_cast<const float2*>(&Psm[k][tx2 * 4 + 2]);
                    float a = Xs[ty2][k];
                    float2 a2 = make_float2(a, a);
                    ffma2(c0, a2, p0);
                    ffma2(c1, a2, p1);
                }
                float4 fj = *reinterpret_cast<const float4*>(&g_F[j][b0 + ty2][i0 + tx2 * 4]);
                float4 xv = make_float4(fj.x + c0.x, fj.y + c0.y, fj.z + c1.x, fj.w + c1.y);
                *reinterpret_cast<float4*>(&g_Xf[par][s & 1][b0 + ty2][i0 + tx2 * 4]) = xv;
                *reinterpret_cast<__half2*>(&g_Xq[j + 1][b0 + ty2][i0 + tx2 * 4]) =
                    __floats2half2_rn(xv.x, xv.y);
                *reinterpret_cast<__half2*>(&g_Xq[j + 1][b0 + ty2][i0 + tx2 * 4 + 2]) =
                    __floats2half2_rn(xv.z, xv.w);
            }
            gbar_on(&g_barctr2, POSTG * (++epoch));
        }
    }
}

// ---------------------------------------------------------------------------
// fused mma kernel (R12 variant): non-persistent grid 4096, PAIR-UNROLLED
// chunks, 4-buffer ring, constant cp_wait<2> per pair, empty groups always
// committed. fp16 single product, zero-chunk skip, evict-first stores.
// ---------------------------------------------------------------------------
#define FST 80          // smem row stride bytes (32 fp16 = 64B + 16 pad)
#define ST_B 10240
#define STAGE_B 20480
#define SMEM_FUSED (4 * STAGE_B)

__global__ void __launch_bounds__(256, 2) k_fused(float* __restrict__ out) {
    extern __shared__ char smbuf[];
    const uint32_t sb = smem_u32(smbuf);
    const int tid = threadIdx.x;
    const int lane = tid & 31, wid = tid >> 5;
    const int wm = wid & 3, wn = wid >> 2;        // 4 x 2 warp grid
    const int bx = blockIdx.x;
    const int r = bx >> 5;                        // 32 consecutive CTAs share P[r+1]
    const int c = (bx >> 1) & 15;
    const int bn = bx & 1;                        // N-half
    const int t = c * CHK + r;

    float acc[2][8][4];
#pragma unroll
    for (int ma = 0; ma < 2; ma++)
#pragma unroll
        for (int nb = 0; nb < 8; nb++)
#pragma unroll
            for (int q = 0; q < 4; q++) acc[ma][nb][q] = 0.f;

    const int nc = (r >> 5) + 1;                  // conv chunks
    const int nact = nc + ((c > 0) ? 8 : 0);      // + X chunks
    const int s8 = (127 - r) & 7;
    const int xbase = 127 - r - s8;               // 8-aligned

    // stage chunk li into buffer li&3; ALWAYS commits (empty group if li>=nact)
    auto stage = [&](int li) {
        if (li < nact) {
            int kc = (li < nc) ? li : (li - nc + 4);
            uint32_t s0 = sb + (uint32_t)(li & 3) * STAGE_B;
            if (kc < 4) {
                int x0 = xbase + kc * 32;
#pragma unroll
                for (int it = 0; it < 2; it++) {
                    int e = it * 256 + tid;
                    int row = e >> 2, v = e & 3;
                    cp16(s0 + row * FST + v * 16, &g_uRq8[s8][c][row][x0 + v * 8]);
                }
#pragma unroll
                for (int it = 0; it < 2; it++) {
                    int e = it * 256 + tid;
                    int row = e >> 2, v = e & 3;
                    cp16(s0 + ST_B + row * FST + v * 16,
                         &g_KTq[bn * 128 + row][kc * 32 + v * 8]);
                }
            } else {
                int kb = (kc - 4) * 32;
#pragma unroll
                for (int it = 0; it < 2; it++) {
                    int e = it * 256 + tid;
                    int row = e >> 2, v = e & 3;
                    cp16(s0 + row * FST + v * 16, &g_Xq[c][row][kb + v * 8]);
                }
#pragma unroll
                for (int it = 0; it < 2; it++) {
                    int e = it * 256 + tid;
                    int row = e >> 2, v = e & 3;
                    cp16(s0 + ST_B + row * FST + v * 16,
                         &g_Pq[r + 1][bn * 128 + row][kb + v * 8]);
                }
            }
        }
        cp_commit();
    };

    auto compute = [&](int buf) {
        uint32_t s0 = sb + (uint32_t)buf * STAGE_B;
        uint32_t aA = s0 + (wm * 32 + (lane & 15)) * FST + (lane >> 4) * 16;
        uint32_t aB = s0 + ST_B + (wn * 64 + (lane & 15)) * FST + (lane >> 4) * 16;
#pragma unroll
        for (int ks = 0; ks < 2; ks++) {
            uint32_t Ah[8];
#pragma unroll
            for (int ma = 0; ma < 2; ma++)
                ldsm4(&Ah[ma * 4], aA + ma * (16 * FST) + ks * 32);
#pragma unroll
            for (int pr = 0; pr < 4; pr++) {
                uint32_t bh[4];
                ldsm4(bh, aB + pr * (16 * FST) + ks * 32);
#pragma unroll
                for (int sub = 0; sub < 2; sub++) {
                    int nb = pr * 2 + sub;
#pragma unroll
                    for (int ma = 0; ma < 2; ma++)
                        mma_f16(acc[ma][nb], &Ah[ma * 4], bh[sub], bh[2 + sub]);
                }
            }
        }
    };

    // prefill 4 groups (some possibly empty)
    stage(0); stage(1); stage(2); stage(3);

    int li = 0;
#pragma unroll 1
    while (li + 1 < nact) {
        cp_wait<2>();
        __syncthreads();
        compute(li & 3);
        compute((li + 1) & 3);
        __syncthreads();
        stage(li + 4);
        stage(li + 5);
        li += 2;
    }
    if (li < nact) {
        cp_wait<0>();
        __syncthreads();
        compute(li & 3);
    }

    // epilogue: evict-first fp32 stores
    float* outt = out + (size_t)t * (B_DIM * N_DIM);
#pragma unroll
    for (int ma = 0; ma < 2; ma++) {
        int row = wm * 32 + ma * 16 + (lane >> 2);
#pragma unroll
        for (int nb = 0; nb < 8; nb++) {
            int col = bn * 128 + wn * 64 + nb * 8 + (lane & 3) * 2;
            __stcs(reinterpret_cast<float2*>(outt + row * 256 + col),
                   make_float2(acc[ma][nb][0], acc[ma][nb][1]));
            __stcs(reinterpret_cast<float2*>(outt + (row + 8) * 256 + col),
                   make_float2(acc[ma][nb][2], acc[ma][nb][3]));
        }
    }
}

// ---------------------------------------------------------------------------
extern "C" void kernel_launch(void* const* d_in, const int* in_sizes, int n_in,
                              void* d_out, int out_size) {
    const float* u  = (const float*)d_in[0];   // [L, B]
    const float* dA = (const float*)d_in[1];   // [N, N]
    const float* dB = (const float*)d_in[2];   // [N]
    float* out = (float*)d_out;                // [L, B, N]

    cudaFuncSetAttribute(k_fused, cudaFuncAttributeMaxDynamicSharedMemorySize, SMEM_FUSED);
    cudaFuncSetAttribute(k_post, cudaFuncAttributeMaxDynamicSharedMemorySize, POST_SMEM);

    k_init<<<256, 256>>>(dA, dB);
    k_powerall<<<PGRID, 256>>>(dB, u);
    k_post<<<POSTG, 256, POST_SMEM>>>(u);
    k_fused<<<2 * L_DIM, 256, SMEM_FUSED>>>(out);
}

// round 14
// speedup vs baseline: 1.1775x; 1.0691x over previous
#include <cuda_runtime.h>
#include <cuda_fp16.h>
#include <cstdint>

// Problem constants
#define N_DIM 256
#define L_DIM 2048
#define B_DIM 128
#define CHK   128
#define NCHUNK 16
#define PGRID 296
#define POSTG 128

// ---------------------------------------------------------------------------
// Device global scratch
// ---------------------------------------------------------------------------
__device__ float g_P2[N_DIM][N_DIM];                // dA^256 fp32 (T^2)
__device__ float g_PT[N_DIM][N_DIM];                // P128^T fp32
__device__ float g_K[CHK][N_DIM];                   // Kvec fp32
__device__ float g_E[NCHUNK][B_DIM][N_DIM];         // chunk-end conv values
__device__ float g_F[NCHUNK][B_DIM][N_DIM];         // F_j = E_j + E_{j-1} T
__device__ float g_Xf[2][2][B_DIM][N_DIM];          // fp32 X ping-pong per parity
__device__ float g_Ppart[256][4096];                // split-K partial tiles
__device__ unsigned g_tilecnt[256];                 // split-K arrival counters
__device__ __half g_Pq[CHK + 1][N_DIM][N_DIM];      // P hi limb (natural [i][k])
__device__ __half g_Pl[CHK + 1][N_DIM][N_DIM];      // P lo limb (natural)
__device__ __half g_KTq[N_DIM][CHK];                // fp16 K transposed
__device__ __half g_uRq8[8][NCHUNK][B_DIM][256];    // 8 byte-shift copies of reversed u
__device__ __half g_Xq[NCHUNK][B_DIM][N_DIM];       // fp16 X_{c-1} (c>=1)
__device__ unsigned g_barctr;
__device__ unsigned g_barctr2;

// ---------------------------------------------------------------------------
// helpers
// ---------------------------------------------------------------------------
__device__ __forceinline__ void ffma2(float2& c, float2 a, float2 b) {
    asm("{\n\t"
        ".reg .b64 ra, rb, rc;\n\t"
        "mov.b64 ra, {%2, %3};\n\t"
        "mov.b64 rb, {%4, %5};\n\t"
        "mov.b64 rc, {%0, %1};\n\t"
        "fma.rn.f32x2 rc, ra, rb, rc;\n\t"
        "mov.b64 {%0, %1}, rc;\n\t"
        "}"
        : "+f"(c.x), "+f"(c.y)
        : "f"(a.x), "f"(a.y), "f"(b.x), "f"(b.y));
}

__device__ __forceinline__ uint32_t smem_u32(const void* p) {
    uint32_t a;
    asm("{ .reg .u64 t; cvta.to.shared.u64 t, %1; cvt.u32.u64 %0, t; }" : "=r"(a) : "l"(p));
    return a;
}

__device__ __forceinline__ void mma_f16(float d[4], const uint32_t a[4],
                                        uint32_t b0, uint32_t b1) {
    asm volatile(
        "mma.sync.aligned.m16n8k16.row.col.f32.f16.f16.f32 "
        "{%0,%1,%2,%3}, {%4,%5,%6,%7}, {%8,%9}, {%0,%1,%2,%3};"
        : "+f"(d[0]), "+f"(d[1]), "+f"(d[2]), "+f"(d[3])
        : "r"(a[0]), "r"(a[1]), "r"(a[2]), "r"(a[3]), "r"(b0), "r"(b1));
}

__device__ __forceinline__ void ldsm4(uint32_t* r, uint32_t addr) {
    asm volatile("ldmatrix.sync.aligned.m8n8.x4.shared.b16 {%0,%1,%2,%3}, [%4];"
                 : "=r"(r[0]), "=r"(r[1]), "=r"(r[2]), "=r"(r[3]) : "r"(addr));
}

__device__ __forceinline__ void ldsm4t(uint32_t* r, uint32_t addr) {
    asm volatile("ldmatrix.sync.aligned.m8n8.x4.trans.shared.b16 {%0,%1,%2,%3}, [%4];"
                 : "=r"(r[0]), "=r"(r[1]), "=r"(r[2]), "=r"(r[3]) : "r"(addr));
}

__device__ __forceinline__ void cp16(uint32_t sdst, const void* gsrc) {
    asm volatile("cp.async.cg.shared.global [%0], [%1], 16;" :: "r"(sdst), "l"(gsrc));
}
__device__ __forceinline__ void cp_commit() {
    asm volatile("cp.async.commit_group;" ::: "memory");
}
template <int NW>
__device__ __forceinline__ void cp_wait() {
    asm volatile("cp.async.wait_group %0;" :: "n"(NW) : "memory");
}
__device__ __forceinline__ void cp_wait_ahead(int ahead) {
    if (ahead >= 2) cp_wait<2>();
    else if (ahead == 1) cp_wait<1>();
    else cp_wait<0>();
}

__device__ __forceinline__ void split_half(float x, __half& h, __half& l) {
    h = __float2half(x);
    l = __float2half(x - __half2float(h));
}

// grid-wide software barriers (monotonic counters; reset each replay in k_init)
__device__ __forceinline__ void gbar_on(unsigned* ctr, unsigned target) {
    __syncthreads();
    if (threadIdx.x == 0) {
        __threadfence();
        atomicAdd(ctr, 1u);
        unsigned v;
        do {
            asm volatile("ld.acquire.gpu.u32 %0, [%1];" : "=r"(v) : "l"(ctr));
        } while (v < target);
    }
    __syncthreads();
}

// ---------------------------------------------------------------------------
// init: P[1] = dA (hi/lo natural), K[0] = dB, counters reset
// ---------------------------------------------------------------------------
__global__ void k_init(const float* __restrict__ dA, const float* __restrict__ dB) {
    int idx = blockIdx.x * 256 + threadIdx.x;
    if (idx == 0) { g_barctr = 0u; g_barctr2 = 0u; }
    if (idx < 256) g_tilecnt[idx] = 0u;
    if (idx < N_DIM * N_DIM) {
        float x = dA[idx];
        __half h, l;
        split_half(x, h, l);
        (&g_Pq[1][0][0])[idx] = h;
        (&g_Pl[1][0][0])[idx] = l;
    }
    if (idx < N_DIM) {
        g_K[0][idx] = dB[idx];
        g_KTq[idx][0] = __float2half(dB[idx]);
    }
}

// ---------------------------------------------------------------------------
// powerall v3: tensor-core fp16 3-split power chain, natural layout only.
// B fragments come from natural [k][n] hi/lo tiles via ldmatrix.trans.
// Tile 64x64, K-chunk 64, 2-stage ring, split-K on early phases.
// Tail: P256 fp32, Kvec (hi+lo reconstruct), PT (hi+lo), 8 shifted uR copies.
// smem per stage: AH(9216) AL(9216) BH(9216) BL(9216) = 36864; x2 + 1KB
// ---------------------------------------------------------------------------
#define PW_AL 9216
#define PW_BH 18432
#define PW_BL 27648
#define PW_STG 36864
#define PW_SMEM (2 * PW_STG + 1024)

__global__ void __launch_bounds__(256, 2) k_powerall(const float* __restrict__ dB,
                                                     const float* __restrict__ u) {
    extern __shared__ char pwsm[];
    const uint32_t sbp = smem_u32(pwsm);
    __shared__ unsigned s_old;
    int tid = threadIdx.x;
    const int lane = tid & 31, wid = tid >> 5;
    const int wm = wid & 1, wn = wid >> 1;   // 2 x 4 warps: tile M64 x N64 (N16/warp)

    // stage K-chunk 64: A = P[jA] rows [m][k] hi/lo, B = P[mB] rows [k][n] hi/lo
    auto stage_t = [&](int jA, int mB, int row0, int col0, int kc_abs, int buf) {
        uint32_t s0 = sbp + (uint32_t)buf * PW_STG;
        int k0 = kc_abs * 64;
#pragma unroll
        for (int it = 0; it < 2; it++) {
            int e = it * 256 + tid;
            int row = e >> 3, v = e & 7;
            cp16(s0 + row * 144 + v * 16, &g_Pq[jA][row0 + row][k0 + v * 8]);
            cp16(s0 + PW_AL + row * 144 + v * 16, &g_Pl[jA][row0 + row][k0 + v * 8]);
            cp16(s0 + PW_BH + row * 144 + v * 16, &g_Pq[mB][k0 + row][col0 + v * 8]);
            cp16(s0 + PW_BL + row * 144 + v * 16, &g_Pl[mB][k0 + row][col0 + v * 8]);
        }
        cp_commit();
    };

    auto compute_t = [&](int buf, float acc[2][2][4]) {
        uint32_t s0 = sbp + (uint32_t)buf * PW_STG;
        uint32_t aA = s0 + (wm * 32 + (lane & 15)) * 144 + (lane >> 4) * 16;
        // trans-B address: row = k, col byte offset within warp's N16 region
        uint32_t aB = s0 + PW_BH
                    + ((lane & 7) + ((lane >> 4) << 3)) * 144
                    + wn * 32 + ((lane >> 3) & 1) * 16;
#pragma unroll
        for (int ks = 0; ks < 4; ks++) {
            uint32_t Ah[8], Al[8];
#pragma unroll
            for (int ma = 0; ma < 2; ma++) {
                ldsm4(&Ah[ma * 4], aA + ma * (16 * 144) + ks * 32);
                ldsm4(&Al[ma * 4], aA + PW_AL + ma * (16 * 144) + ks * 32);
            }
            uint32_t bh[4], bl[4];
            ldsm4t(bh, aB + ks * 16 * 144);
            ldsm4t(bl, aB + (PW_BL - PW_BH) + ks * 16 * 144);
#pragma unroll
            for (int nb = 0; nb < 2; nb++) {
                uint32_t bh0 = (nb == 0) ? bh[0] : bh[1];
                uint32_t bh1 = (nb == 0) ? bh[2] : bh[3];
                uint32_t bl0 = (nb == 0) ? bl[0] : bl[1];
                uint32_t bl1 = (nb == 0) ? bl[2] : bl[3];
#pragma unroll
                for (int ma = 0; ma < 2; ma++) {
                    mma_f16(acc[ma][nb], &Ah[ma * 4], bh0, bh1);
                    mma_f16(acc[ma][nb], &Ah[ma * 4], bl0, bl1);
                    mma_f16(acc[ma][nb], &Al[ma * 4], bh0, bh1);
                }
            }
        }
    };

    auto tile_t = [&](int jA, int mB, int row0, int col0, int kc0, int nkc,
                      float acc[2][2][4]) {
#pragma unroll
        for (int ma = 0; ma < 2; ma++)
#pragma unroll
            for (int nb = 0; nb < 2; nb++)
#pragma unroll
                for (int q = 0; q < 4; q++) acc[ma][nb][q] = 0.f;
        stage_t(jA, mB, row0, col0, kc0, 0);
#pragma unroll 1
        for (int kc = 0; kc < nkc; kc++) {
            if (kc + 1 < nkc) {
                stage_t(jA, mB, row0, col0, kc0 + kc + 1, (kc + 1) & 1);
                cp_wait<1>();
            } else {
                cp_wait<0>();
            }
            __syncthreads();
            compute_t(kc & 1, acc);
            __syncthreads();
        }
    };

    // epilogue: coalesced hi/lo natural stores only
    auto epi_full = [&](int d, int row0, int col0, float acc[2][2][4]) {
#pragma unroll
        for (int ma = 0; ma < 2; ma++) {
#pragma unroll
            for (int nb = 0; nb < 2; nb++) {
                int row = row0 + wm * 32 + ma * 16 + (lane >> 2);
                int col = col0 + wn * 16 + nb * 8 + (lane & 3) * 2;
#pragma unroll
                for (int h = 0; h < 2; h++) {
                    int rr = row + h * 8;
                    __half h0, l0, h1, l1;
                    split_half(acc[ma][nb][h * 2 + 0], h0, l0);
                    split_half(acc[ma][nb][h * 2 + 1], h1, l1);
                    *reinterpret_cast<__half2*>(&g_Pq[d][rr][col]) = __halves2half2(h0, h1);
                    *reinterpret_cast<__half2*>(&g_Pl[d][rr][col]) = __halves2half2(l0, l1);
                }
            }
        }
    };

    const int SPL[7] = {4, 4, 2, 2, 1, 1, 1};

    for (int ph = 0; ph < 7; ph++) {
        int m = 1 << ph;
        int sk = SPL[ph];
        int ntile = 16 * m;
        int nwork = ntile * sk;
        int nkc = 4 / sk;
        for (int w = blockIdx.x; w < nwork; w += PGRID) {
            int tile = w / sk, slice = w - tile * sk;
            int j = (tile >> 4) + 1, ti = tile & 15;
            int row0 = (ti >> 2) * 64, col0 = (ti & 3) * 64;
            float acc[2][2][4];
            tile_t(j, m, row0, col0, slice * nkc, nkc, acc);

            if (sk == 1) {
                epi_full(m + j, row0, col0, acc);
            } else {
                // fp32 partial
#pragma unroll
                for (int ma = 0; ma < 2; ma++)
#pragma unroll
                    for (int nb = 0; nb < 2; nb++) {
                        int rl = wm * 32 + ma * 16 + (lane >> 2);
                        int cl = wn * 16 + nb * 8 + (lane & 3) * 2;
                        *reinterpret_cast<float2*>(&g_Ppart[w][rl * 64 + cl]) =
                            make_float2(acc[ma][nb][0], acc[ma][nb][1]);
                        *reinterpret_cast<float2*>(&g_Ppart[w][(rl + 8) * 64 + cl]) =
                            make_float2(acc[ma][nb][2], acc[ma][nb][3]);
                    }
                __syncthreads();
                if (tid == 0) {
                    __threadfence();
                    s_old = atomicAdd(&g_tilecnt[tile], 1u);
                }
                __syncthreads();
                if (s_old == (unsigned)(sk - 1)) {
                    // deterministic last-arriver reduction, coalesced hi/lo out
                    int d = m + j;
#pragma unroll 1
                    for (int e = tid; e < 4096; e += 256) {
                        int rl = e >> 6, cl = e & 63;
                        float vs = 0.f;
                        for (int s2 = 0; s2 < sk; s2++)
                            vs += __ldcg(&g_Ppart[tile * sk + s2][e]);
                        __half h, l;
                        split_half(vs, h, l);
                        g_Pq[d][row0 + rl][col0 + cl] = h;
                        g_Pl[d][row0 + rl][col0 + cl] = l;
                    }
                    __syncthreads();
                    if (tid == 0) g_tilecnt[tile] = 0u;
                }
            }
        }
        gbar_on(&g_barctr, PGRID * (unsigned)(ph + 1));
    }

    // ---- tail (disjoint CTA ranges) ----
    int bx = blockIdx.x;
    if (bx < 16) {
        // P256 = P128 @ P128 (fp32 out for parity scan)
        int row0 = (bx >> 2) * 64, col0 = (bx & 3) * 64;
        float acc[2][2][4];
        tile_t(CHK, CHK, row0, col0, 0, 4, acc);
#pragma unroll
        for (int ma = 0; ma < 2; ma++)
#pragma unroll
            for (int nb = 0; nb < 2; nb++) {
                int row = row0 + wm * 32 + ma * 16 + (lane >> 2);
                int col = col0 + wn * 16 + nb * 8 + (lane & 3) * 2;
                *reinterpret_cast<float2*>(&g_P2[row][col]) =
                    make_float2(acc[ma][nb][0], acc[ma][nb][1]);
                *reinterpret_cast<float2*>(&g_P2[row + 8][col]) =
                    make_float2(acc[ma][nb][2], acc[ma][nb][3]);
            }
    } else if (bx < 143) {
        // Kvec: K[k] = P[k] @ dB, P reconstructed hi+lo
        float* sDB = reinterpret_cast<float*>(pwsm + 2 * PW_STG);
        sDB[tid] = dB[tid];
        __syncthreads();
        int k = bx - 15;
        int i = tid;
        const __half2* rh = reinterpret_cast<const __half2*>(&g_Pq[k][i][0]);
        const __half2* rl = reinterpret_cast<const __half2*>(&g_Pl[k][i][0]);
        float acc = 0.0f;
#pragma unroll 8
        for (int jj = 0; jj < 128; jj++) {
            float2 ah = __half22float2(rh[jj]);
            float2 al = __half22float2(rl[jj]);
            acc += (ah.x + al.x) * sDB[2 * jj] + (ah.y + al.y) * sDB[2 * jj + 1];
        }
        g_K[k][i] = acc;
        g_KTq[i][k] = __float2half(acc);
    } else if (bx < 159) {
        // PT fp32: PT[k][i] = P128[i][k] = hi + lo
        int base = (bx - 143) * 4096 + tid * 16;
#pragma unroll
        for (int q = 0; q < 16; q++) {
            int e = base + q;
            int k = e >> 8, i = e & 255;
            (&g_PT[0][0])[e] =
                __half2float(g_Pq[CHK][i][k]) + __half2float(g_Pl[CHK][i][k]);
        }
    } else {
        // 8 shifted reversed-u fp16 copies
        const int total8 = 8 * NCHUNK * B_DIM * 256;
        for (int idx = (bx - 159) * 256 + tid; idx < total8;
             idx += (PGRID - 159) * 256) {
            int s = idx >> 19;
            int rem = idx & ((1 << 19) - 1);
            int c = rem >> 15;
            int b = (rem >> 8) & 127;
            int x = rem & 255;
            int q = x + s;
            float v = (q <= 127) ? u[(c * CHK + 127 - q) * B_DIM + b] : 0.0f;
            g_uRq8[s][c][b][x] = __float2half(v);
        }
    }
}

// ---------------------------------------------------------------------------
// k_post: etail + fprep + parity-scan fused in one launch (grid barriers).
// (unchanged from R13)
// ---------------------------------------------------------------------------
#define POST_SMEM (256 * 34 * 4 + 32 * 260 * 4)

__global__ void __launch_bounds__(256, 1) k_post(const float* __restrict__ u) {
    extern __shared__ float sp[];
    int tid = threadIdx.x, tx = tid & 15, ty = tid >> 4;
    int bx = blockIdx.x;
    unsigned epoch = 0;

    // ================= phase 1: etail =================
    {
        int j = bx >> 3;
        int b0 = ((bx >> 2) & 1) * 64, i0 = (bx & 3) * 64;
        int t0 = j * CHK;
        float (*Ast)[16][68] = reinterpret_cast<float(*)[16][68]>(sp);
        float (*Bss)[16][68] = reinterpret_cast<float(*)[16][68]>(sp + 4 * 16 * 68);
        auto issue = [&](int kc) {
            int s = kc & 3, k0 = kc * 16;
            int kk = tid >> 4, v = tid & 15;
            cp16(smem_u32(&Ast[s][kk][v * 4]),
                 &u[(t0 + 127 - (k0 + kk)) * B_DIM + b0 + v * 4]);
            cp16(smem_u32(&Bss[s][kk][v * 4]), &g_K[k0 + kk][i0 + v * 4]);
            cp_commit();
        };
        issue(0); issue(1); issue(2);
        float2 acc[4][2] = {};
#pragma unroll 1
        for (int kc = 0; kc < 8; kc++) {
            cp_wait_ahead(7 - kc);
            __syncthreads();
            if (kc + 3 < 8) issue(kc + 3);
            int s = kc & 3;
#pragma unroll
            for (int kk = 0; kk < 16; kk++) {
                float2 b0v = *reinterpret_cast<const float2*>(&Bss[s][kk][tx * 4]);
                float2 b1v = *reinterpret_cast<const float2*>(&Bss[s][kk][tx * 4 + 2]);
#pragma unroll
                for (int ii = 0; ii < 4; ii++) {
                    float a = Ast[s][kk][ty * 4 + ii];
                    float2 a2 = make_float2(a, a);
                    ffma2(acc[ii][0], a2, b0v);
                    ffma2(acc[ii][1], a2, b1v);
                }
            }
        }
        __syncthreads();
#pragma unroll
        for (int ii = 0; ii < 4; ii++) {
            *reinterpret_cast<float4*>(&g_E[j][b0 + ty * 4 + ii][i0 + tx * 4]) =
                make_float4(acc[ii][0].x, acc[ii][0].y, acc[ii][1].x, acc[ii][1].y);
        }
    }
    gbar_on(&g_barctr2, POSTG * (++epoch));

    // ================= phase 2: fprep =================
    if (bx < 120) {
        int j = (bx >> 3) + 1;
        int b0 = ((bx >> 2) & 1) * 64, i0 = (bx & 3) * 64;
        const float* __restrict__ A = &g_E[j - 1][0][0];
        const float* __restrict__ B = &g_PT[0][0];
        float (*As)[64][20] = reinterpret_cast<float(*)[64][20]>(sp);
        float (*Bss)[16][68] = reinterpret_cast<float(*)[16][68]>(sp + 4 * 64 * 20);
        auto issue = [&](int kc) {
            int s = kc & 3, k0 = kc * 16;
            {
                int row = tid >> 2, v = tid & 3;
                cp16(smem_u32(&As[s][row][v * 4]), &A[(b0 + row) * N_DIM + k0 + v * 4]);
            }
            {
                int row = tid >> 4, v = tid & 15;
                cp16(smem_u32(&Bss[s][row][v * 4]), &B[(k0 + row) * N_DIM + i0 + v * 4]);
            }
            cp_commit();
        };
        issue(0); issue(1); issue(2);
        float2 acc[4][2] = {};
#pragma unroll 1
        for (int kc = 0; kc < 16; kc++) {
            cp_wait_ahead(15 - kc);
            __syncthreads();
            if (kc + 3 < 16) issue(kc + 3);
            int s = kc & 3;
#pragma unroll
            for (int kk4 = 0; kk4 < 4; kk4++) {
                float4 a4[4];
#pragma unroll
                for (int ii = 0; ii < 4; ii++)
                    a4[ii] = *reinterpret_cast<const float4*>(&As[s][ty * 4 + ii][kk4 * 4]);
#pragma unroll
                for (int q = 0; q < 4; q++) {
                    int kk = kk4 * 4 + q;
                    float2 b0v = *reinterpret_cast<const float2*>(&Bss[s][kk][tx * 4]);
                    float2 b1v = *reinterpret_cast<const float2*>(&Bss[s][kk][tx * 4 + 2]);
#pragma unroll
                    for (int ii = 0; ii < 4; ii++) {
                        float av = (q == 0) ? a4[ii].x : (q == 1) ? a4[ii].y
                                 : (q == 2) ? a4[ii].z : a4[ii].w;
                        float2 a2 = make_float2(av, av);
                        ffma2(acc[ii][0], a2, b0v);
                        ffma2(acc[ii][1], a2, b1v);
                    }
                }
            }
        }
        __syncthreads();
#pragma unroll
        for (int ii = 0; ii < 4; ii++) {
            int b = b0 + ty * 4 + ii;
            float4 e = *reinterpret_cast<const float4*>(&g_E[j][b][i0 + tx * 4]);
            *reinterpret_cast<float4*>(&g_F[j][b][i0 + tx * 4]) =
                make_float4(e.x + acc[ii][0].x, e.y + acc[ii][0].y,
                            e.z + acc[ii][1].x, e.w + acc[ii][1].y);
        }
    }
    gbar_on(&g_barctr2, POSTG * (++epoch));

    // ================= phase 3: parity scan =================
    {
        bool sact = bx < 64;
        int par = bx & 1, tb = bx >> 1;
        int b0 = (tb >> 3) * 32, i0 = (tb & 7) * 32;
        float (*Psm)[34] = reinterpret_cast<float(*)[34]>(sp);
        float (*Xs)[260] = reinterpret_cast<float(*)[260]>(sp + 256 * 34);

        if (sact) {
#pragma unroll
            for (int it = 0; it < 8; it++) {
                int e = it * 256 + tid;
                int ir = e >> 6, v = e & 63;
                float4 x = *reinterpret_cast<const float4*>(&g_P2[i0 + ir][v * 4]);
                Psm[v * 4 + 0][ir] = x.x;
                Psm[v * 4 + 1][ir] = x.y;
                Psm[v * 4 + 2][ir] = x.z;
                Psm[v * 4 + 3][ir] = x.w;
            }
            int r = tid >> 3, v = tid & 7;
            const float* src = (par == 0) ? &g_E[0][0][0] : &g_F[1][0][0];
            float4 x0 = *reinterpret_cast<const float4*>(src + (b0 + r) * N_DIM + i0 + v * 4);
            *reinterpret_cast<float4*>(&g_Xf[par][0][b0 + r][i0 + v * 4]) = x0;
            *reinterpret_cast<__half2*>(&g_Xq[1 + par][b0 + r][i0 + v * 4]) =
                __floats2half2_rn(x0.x, x0.y);
            *reinterpret_cast<__half2*>(&g_Xq[1 + par][b0 + r][i0 + v * 4 + 2]) =
                __floats2half2_rn(x0.z, x0.w);
        }
        gbar_on(&g_barctr2, POSTG * (++epoch));

        int ty2 = tid >> 3, tx2 = tid & 7;
        for (int s = 1; s <= 7; s++) {
            int j = 2 * s + par;
            bool active = sact && ((par == 0) ? (s <= 7) : (s <= 6));
            if (active) {
                const float* src = &g_Xf[par][(s - 1) & 1][0][0];
#pragma unroll
                for (int it = 0; it < 8; it++) {
                    int e = it * 256 + tid;
                    int r = e >> 6, v = e & 63;
                    float4 x = *reinterpret_cast<const float4*>(src + (b0 + r) * N_DIM + v * 4);
                    *reinterpret_cast<float4*>(&Xs[r][v * 4]) = x;
                }
                __syncthreads();
                float2 c0 = make_float2(0.f, 0.f), c1 = make_float2(0.f, 0.f);
#pragma unroll 4
                for (int k = 0; k < 256; k++) {
                    float2 p0 = *reinterpret_cast<const float2*>(&Psm[k][tx2 * 4]);
                    float2 p1 = *reinterpret_cast<const float2*>(&Psm[k][tx2 * 4 + 2]);
                    float a = Xs[ty2][k];
                    float2 a2 = make_float2(a, a);
                    ffma2(c0, a2, p0);
                    ffma2(c1, a2, p1);
                }
                float4 fj = *reinterpret_cast<const float4*>(&g_F[j][b0 + ty2][i0 + tx2 * 4]);
                float4 xv = make_float4(fj.x + c0.x, fj.y + c0.y, fj.z + c1.x, fj.w + c1.y);
                *reinterpret_cast<float4*>(&g_Xf[par][s & 1][b0 + ty2][i0 + tx2 * 4]) = xv;
                *reinterpret_cast<__half2*>(&g_Xq[j + 1][b0 + ty2][i0 + tx2 * 4]) =
                    __floats2half2_rn(xv.x, xv.y);
                *reinterpret_cast<__half2*>(&g_Xq[j + 1][b0 + ty2][i0 + tx2 * 4 + 2]) =
                    __floats2half2_rn(xv.z, xv.w);
            }
            gbar_on(&g_barctr2, POSTG * (++epoch));
        }
    }
}

// ---------------------------------------------------------------------------
// fused mma kernel (unchanged from R13): non-persistent grid 4096,
// PAIR-UNROLLED chunks, 4-buffer ring, constant cp_wait<2> per pair,
// empty groups always committed. fp16 single product, stcs epilogue.
// ---------------------------------------------------------------------------
#define FST 80          // smem row stride bytes (32 fp16 = 64B + 16 pad)
#define ST_B 10240
#define STAGE_B 20480
#define SMEM_FUSED (4 * STAGE_B)

__global__ void __launch_bounds__(256, 2) k_fused(float* __restrict__ out) {
    extern __shared__ char smbuf[];
    const uint32_t sb = smem_u32(smbuf);
    const int tid = threadIdx.x;
    const int lane = tid & 31, wid = tid >> 5;
    const int wm = wid & 3, wn = wid >> 2;        // 4 x 2 warp grid
    const int bx = blockIdx.x;
    const int r = bx >> 5;                        // 32 consecutive CTAs share P[r+1]
    const int c = (bx >> 1) & 15;
    const int bn = bx & 1;                        // N-half
    const int t = c * CHK + r;

    float acc[2][8][4];
#pragma unroll
    for (int ma = 0; ma < 2; ma++)
#pragma unroll
        for (int nb = 0; nb < 8; nb++)
#pragma unroll
            for (int q = 0; q < 4; q++) acc[ma][nb][q] = 0.f;

    const int nc = (r >> 5) + 1;                  // conv chunks
    const int nact = nc + ((c > 0) ? 8 : 0);      // + X chunks
    const int s8 = (127 - r) & 7;
    const int xbase = 127 - r - s8;               // 8-aligned

    auto stage = [&](int li) {
        if (li < nact) {
            int kc = (li < nc) ? li : (li - nc + 4);
            uint32_t s0 = sb + (uint32_t)(li & 3) * STAGE_B;
            if (kc < 4) {
                int x0 = xbase + kc * 32;
#pragma unroll
                for (int it = 0; it < 2; it++) {
                    int e = it * 256 + tid;
                    int row = e >> 2, v = e & 3;
                    cp16(s0 + row * FST + v * 16, &g_uRq8[s8][c][row][x0 + v * 8]);
                }
#pragma unroll
                for (int it = 0; it < 2; it++) {
                    int e = it * 256 + tid;
                    int row = e >> 2, v = e & 3;
                    cp16(s0 + ST_B + row * FST + v * 16,
                         &g_KTq[bn * 128 + row][kc * 32 + v * 8]);
                }
            } else {
                int kb = (kc - 4) * 32;
#pragma unroll
                for (int it = 0; it < 2; it++) {
                    int e = it * 256 + tid;
                    int row = e >> 2, v = e & 3;
                    cp16(s0 + row * FST + v * 16, &g_Xq[c][row][kb + v * 8]);
                }
#pragma unroll
                for (int it = 0; it < 2; it++) {
                    int e = it * 256 + tid;
                    int row = e >> 2, v = e & 3;
                    cp16(s0 + ST_B + row * FST + v * 16,
                         &g_Pq[r + 1][bn * 128 + row][kb + v * 8]);
                }
            }
        }
        cp_commit();
    };

    auto compute = [&](int buf) {
        uint32_t s0 = sb + (uint32_t)buf * STAGE_B;
        uint32_t aA = s0 + (wm * 32 + (lane & 15)) * FST + (lane >> 4) * 16;
        uint32_t aB = s0 + ST_B + (wn * 64 + (lane & 15)) * FST + (lane >> 4) * 16;
#pragma unroll
        for (int ks = 0; ks < 2; ks++) {
            uint32_t Ah[8];
#pragma unroll
            for (int ma = 0; ma < 2; ma++)
                ldsm4(&Ah[ma * 4], aA + ma * (16 * FST) + ks * 32);
#pragma unroll
            for (int pr = 0; pr < 4; pr++) {
                uint32_t bh[4];
                ldsm4(bh, aB + pr * (16 * FST) + ks * 32);
#pragma unroll
                for (int sub = 0; sub < 2; sub++) {
                    int nb = pr * 2 + sub;
#pragma unroll
                    for (int ma = 0; ma < 2; ma++)
                        mma_f16(acc[ma][nb], &Ah[ma * 4], bh[sub], bh[2 + sub]);
                }
            }
        }
    };

    stage(0); stage(1); stage(2); stage(3);

    int li = 0;
#pragma unroll 1
    while (li + 1 < nact) {
        cp_wait<2>();
        __syncthreads();
        compute(li & 3);
        compute((li + 1) & 3);
        __syncthreads();
        stage(li + 4);
        stage(li + 5);
        li += 2;
    }
    if (li < nact) {
        cp_wait<0>();
        __syncthreads();
        compute(li & 3);
    }

    float* outt = out + (size_t)t * (B_DIM * N_DIM);
#pragma unroll
    for (int ma = 0; ma < 2; ma++) {
        int row = wm * 32 + ma * 16 + (lane >> 2);
#pragma unroll
        for (int nb = 0; nb < 8; nb++) {
            int col = bn * 128 + wn * 64 + nb * 8 + (lane & 3) * 2;
            __stcs(reinterpret_cast<float2*>(outt + row * 256 + col),
                   make_float2(acc[ma][nb][0], acc[ma][nb][1]));
            __stcs(reinterpret_cast<float2*>(outt + (row + 8) * 256 + col),
                   make_float2(acc[ma][nb][2], acc[ma][nb][3]));
        }
    }
}

// ---------------------------------------------------------------------------
extern "C" void kernel_launch(void* const* d_in, const int* in_sizes, int n_in,
                              void* d_out, int out_size) {
    const float* u  = (const float*)d_in[0];   // [L, B]
    const float* dA = (const float*)d_in[1];   // [N, N]
    const float* dB = (const float*)d_in[2];   // [N]
    float* out = (float*)d_out;                // [L, B, N]

    cudaFuncSetAttribute(k_fused, cudaFuncAttributeMaxDynamicSharedMemorySize, SMEM_FUSED);
    cudaFuncSetAttribute(k_post, cudaFuncAttributeMaxDynamicSharedMemorySize, POST_SMEM);
    cudaFuncSetAttribute(k_powerall, cudaFuncAttributeMaxDynamicSharedMemorySize, PW_SMEM);

    k_init<<<256, 256>>>(dA, dB);
    k_powerall<<<PGRID, 256, PW_SMEM>>>(dB, u);
    k_post<<<POSTG, 256, POST_SMEM>>>(u);
    k_fused<<<2 * L_DIM, 256, SMEM_FUSED>>>(out);
}